// round 12
// baseline (speedup 1.0000x reference)
#include <cuda_runtime.h>
#include <cstdint>

// SVConvTranspose2d, round 12: R8 body + 4-way Cin block-split to kill
// wave quantization (1024 blocks / 592 concurrent = 1.73 waves -> 13% idle;
// 4096 blocks -> 6.92 waves -> ~1%). Cross-block Cin reduce via atomicAdd
// (L2-resident out), bias pre-filled by a tiny init kernel.
//
// x:      (4, 16, 128, 128) f32        -- 4 MB, L2-hot
// weight: (16, 16, 5, 5, 128, 128) f32 -- 419 MB DRAM-read exactly once
//                                         (i-slices disjoint across blocks)
// bias:   (1, 16, 1, 1) f32
// out:    (4, 16, 128, 128) f32
//
// out[n,o,oh,ow] = bias[o] + sum wt[i,o,kh,kw,h,w] * x[n,i,h,w],
//   h = oh+2-kh (gather), ow = w+kw-2 (scatter into acc window).
//
// Block = 256 thr = (ih:2 sub-slices of 2 i) x (np:2 batch-pairs)
//                   x (o2:2 outs) x (q:32 quads); block owns 4 of 16 i.
// Grid  = 128 rows x 8 o-pairs x 4 i-slices = 4096 blocks.
// Hot loop per (kh,ii): 5 weight LDG.128 batched FIRST, then 2 x LDG.128,
// then 40 FMA. np twin warps dedup weight reads in L1 (verified R7/R8).

#define H_  128
#define W_  128
#define HW  16384

__global__ __launch_bounds__(256)
void init_out(const float* __restrict__ bias, float* __restrict__ out)
{
    const int idx = blockIdx.x * 256 + threadIdx.x;       // 262144 float4s
    const float b = __ldg(bias + ((idx >> 12) & 15));
    ((float4*)out)[idx] = make_float4(b, b, b, b);
}

__global__ __launch_bounds__(256, 4)
void svct_kernel(const float* __restrict__ x,
                 const float* __restrict__ wt,
                 float* __restrict__ out)
{
    __shared__ float red[2][2][2][2][W_];   // [o2][np][m][ih][w]  8 KB

    const int t   = threadIdx.x;
    const int q   = t & 31;              // quad index in row == lane
    const int o2  = (t >> 5) & 1;        // which of the 2 outs
    const int np  = (t >> 6) & 1;        // batch pair: n in {2np, 2np+1}
    const int ih  = (t >> 7) & 1;        // sub-slice of 2 i
    const int oh  = blockIdx.x >> 5;     // output row
    const int og  = (blockIdx.x >> 2) & 7; // o-pair
    const int ib  = blockIdx.x & 3;      // i-slice of 4
    const int oc  = og * 2 + o2;         // output channel
    const int n0  = np * 2;
    const int ibase = ib * 4 + ih * 2;   // this thread's first input channel

    float acc[2][8];                     // [m][window k]
    #pragma unroll
    for (int m = 0; m < 2; m++)
        #pragma unroll
        for (int k = 0; k < 8; k++)
            acc[m][k] = 0.0f;

    #pragma unroll 1
    for (int kh = 0; kh < 5; kh++) {
        const int h = oh + 2 - kh;
        if ((unsigned)h >= (unsigned)H_) continue;

        #pragma unroll
        for (int ii = 0; ii < 2; ii++) {
            const int i = ibase + ii;

            // Weight batch FIRST: 5 aligned quads, 5 independent DRAM lines
            // in flight per warp. __ldg so the twin np-warp hits L1.
            const long wrow = ((long)((i * 16 + oc) * 5 + kh) * 5) * HW + (long)h * W_;
            float4 w4[5];
            #pragma unroll
            for (int kw = 0; kw < 5; kw++)
                w4[kw] = __ldg((const float4*)(wt + wrow + (long)kw * HW) + q);

            // Then 2 L2-hot x quads at the same spatial position.
            float4 xq[2];
            #pragma unroll
            for (int m = 0; m < 2; m++)
                xq[m] = __ldg((const float4*)x + (((n0 + m) * 16 + i) * H_ + h) * 32 + q);

            #pragma unroll
            for (int kw = 0; kw < 5; kw++) {
                const float wv[4] = {w4[kw].x, w4[kw].y, w4[kw].z, w4[kw].w};
                #pragma unroll
                for (int m = 0; m < 2; m++) {
                    const float xv[4] = {xq[m].x, xq[m].y, xq[m].z, xq[m].w};
                    #pragma unroll
                    for (int j = 0; j < 4; j++)
                        acc[m][j + kw] = fmaf(wv[j], xv[j], acc[m][j + kw]);
                }
            }
        }
    }

    // cross-lane combine (4 shuffles per m), then smem-reduce the 2 ih slices
    const bool q0  = (q == 0);
    const bool q31 = (q == 31);
    #pragma unroll
    for (int m = 0; m < 2; m++) {
        float up6 = __shfl_up_sync(0xffffffffu, acc[m][6], 1);
        float up7 = __shfl_up_sync(0xffffffffu, acc[m][7], 1);
        float dn0 = __shfl_down_sync(0xffffffffu, acc[m][0], 1);
        float dn1 = __shfl_down_sync(0xffffffffu, acc[m][1], 1);
        if (q0)  { up6 = 0.0f; up7 = 0.0f; }
        if (q31) { dn0 = 0.0f; dn1 = 0.0f; }
        *(float4*)&red[o2][np][m][ih][4 * q] =
            make_float4(acc[m][2] + up6, acc[m][3] + up7,
                        acc[m][4] + dn0, acc[m][5] + dn1);
    }
    __syncthreads();

    // 256 writer threads: (o2w:2) x (nw:4) x (qw:32); accumulate into out
    const int o2w = t >> 7;
    const int nw  = (t >> 5) & 3;
    const int qw  = t & 31;
    const int ocw = og * 2 + o2w;

    float4 s0 = *(const float4*)&red[o2w][nw >> 1][nw & 1][0][4 * qw];
    float4 s1 = *(const float4*)&red[o2w][nw >> 1][nw & 1][1][4 * qw];

    float* op = out + (((long)(nw * 16 + ocw) * H_ + oh) * W_ + 4 * qw);
    atomicAdd(op + 0, s0.x + s1.x);
    atomicAdd(op + 1, s0.y + s1.y);
    atomicAdd(op + 2, s0.z + s1.z);
    atomicAdd(op + 3, s0.w + s1.w);
}

extern "C" void kernel_launch(void* const* d_in, const int* in_sizes, int n_in,
                              void* d_out, int out_size)
{
    const float* x    = (const float*)d_in[0];
    const float* wt   = (const float*)d_in[1];
    const float* bias = (const float*)d_in[2];
    float*       out  = (float*)d_out;

    init_out<<<1024, 256>>>(bias, out);
    svct_kernel<<<4096, 256>>>(x, wt, out);
}

// round 13
// speedup vs baseline: 1.2377x; 1.2377x over previous
#include <cuda_runtime.h>

// SVConvTranspose2d, round 13: R4/R8 body in HALF-SIZE blocks so the whole
// grid fits in ONE wave.
//   R4: 1024 blocks x 256thr @4/SM -> 592 concurrent -> 1.73 waves (86.5%).
//   R13: 1024 blocks x 128thr @7/SM -> 1036 concurrent -> 1 wave (~99%).
// Same 28 warps/SM, same 5-deep weight batch -> same intra-wave DRAM rate,
// no longer diluted by the wave tail.
//
// x:      (4, 16, 128, 128) f32        -- 4 MB, L2-hot
// weight: (16, 16, 5, 5, 128, 128) f32 -- 419 MB, read EXACTLY once (ldcs)
// bias:   (1, 16, 1, 1) f32
// out:    (4, 16, 128, 128) f32
//
// out[n,o,oh,ow] = bias[o] + sum wt[i,o,kh,kw,h,w] * x[n,i,h,w],
//   h = oh+2-kh (gather), ow = w+kw-2 (scatter into acc window).
//
// Thread = (q:32 quads, o2:2 outs, ih:2 i-slices of 8); all 4 batches.
// acc[4][8] window over out positions [4q-2,4q+6): tap (kw,j) -> j+kw.
// Hot loop per (kh,ii): 5 weight LDG.128 batched FIRST, then x in two
// 2-quad sub-batches (keeps peak regs ~60 under the 72-reg cap).
// Grid = 128 rows x 8 o-pairs = 1024 blocks of 128 threads.

#define H_  128
#define W_  128
#define HW  16384

__global__ __launch_bounds__(128, 7)
void svct_kernel(const float* __restrict__ x,
                 const float* __restrict__ wt,
                 const float* __restrict__ bias,
                 float* __restrict__ out)
{
    __shared__ float red[2][4][2][W_];   // [o2][n][ih][w]  4 KB

    const int t   = threadIdx.x;
    const int q   = t & 31;              // quad index in row == lane
    const int o2  = (t >> 5) & 1;        // which of the 2 outs
    const int ih  = (t >> 6) & 1;        // i-slice of 8
    const int oh  = blockIdx.x >> 3;     // output row
    const int og  = blockIdx.x & 7;      // o-pair
    const int oc  = og * 2 + o2;         // output channel
    const int ibase = ih * 8;

    float acc[4][8];                     // [n][window k]
    #pragma unroll
    for (int n = 0; n < 4; n++)
        #pragma unroll
        for (int k = 0; k < 8; k++)
            acc[n][k] = 0.0f;

    #pragma unroll 1
    for (int kh = 0; kh < 5; kh++) {
        const int h = oh + 2 - kh;
        if ((unsigned)h >= (unsigned)H_) continue;

        #pragma unroll 1
        for (int ii = 0; ii < 8; ii++) {
            const int i = ibase + ii;

            // Weight batch FIRST: 5 aligned quads = 5 independent DRAM
            // lines in flight per warp. Streaming: read-once 419 MB.
            const long wrow = ((long)((i * 16 + oc) * 5 + kh) * 5) * HW + (long)h * W_;
            float4 w4[5];
            #pragma unroll
            for (int kw = 0; kw < 5; kw++)
                w4[kw] = __ldcs((const float4*)(wt + wrow + (long)kw * HW) + q);

            // x in two 2-quad sub-batches to keep peak regs ~60.
            #pragma unroll
            for (int half = 0; half < 2; half++) {
                float4 xq[2];
                #pragma unroll
                for (int m = 0; m < 2; m++)
                    xq[m] = __ldg((const float4*)x
                                  + (((half * 2 + m) * 16 + i) * H_ + h) * 32 + q);

                #pragma unroll
                for (int kw = 0; kw < 5; kw++) {
                    const float wv[4] = {w4[kw].x, w4[kw].y, w4[kw].z, w4[kw].w};
                    #pragma unroll
                    for (int m = 0; m < 2; m++) {
                        const int n = half * 2 + m;
                        const float xv[4] = {xq[m].x, xq[m].y, xq[m].z, xq[m].w};
                        #pragma unroll
                        for (int j = 0; j < 4; j++)
                            acc[n][j + kw] = fmaf(wv[j], xv[j], acc[n][j + kw]);
                    }
                }
            }
        }
    }

    // cross-lane combine (4 shuffles per n), then smem-reduce the 2 i-slices
    const bool q0  = (q == 0);
    const bool q31 = (q == 31);
    #pragma unroll
    for (int n = 0; n < 4; n++) {
        float up6 = __shfl_up_sync(0xffffffffu, acc[n][6], 1);
        float up7 = __shfl_up_sync(0xffffffffu, acc[n][7], 1);
        float dn0 = __shfl_down_sync(0xffffffffu, acc[n][0], 1);
        float dn1 = __shfl_down_sync(0xffffffffu, acc[n][1], 1);
        if (q0)  { up6 = 0.0f; up7 = 0.0f; }
        if (q31) { dn0 = 0.0f; dn1 = 0.0f; }
        *(float4*)&red[o2][n][ih][4 * q] =
            make_float4(acc[n][2] + up6, acc[n][3] + up7,
                        acc[n][4] + dn0, acc[n][5] + dn1);
    }
    __syncthreads();

    // 128 threads write 256 float4 outputs: 2 per thread
    #pragma unroll
    for (int rep = 0; rep < 2; rep++) {
        const int idx = t + rep * 128;        // (o2w:2)(nw:4)(qw:32)
        const int o2w = idx >> 7;
        const int nw  = (idx >> 5) & 3;
        const int qw  = idx & 31;
        const int ocw = og * 2 + o2w;

        float4 s0 = *(const float4*)&red[o2w][nw][0][4 * qw];
        float4 s1 = *(const float4*)&red[o2w][nw][1][4 * qw];

        const float b = __ldg(bias + ocw);
        float4 r;
        r.x = s0.x + s1.x + b;
        r.y = s0.y + s1.y + b;
        r.z = s0.z + s1.z + b;
        r.w = s0.w + s1.w + b;

        ((float4*)out)[((nw * 16 + ocw) * H_ + oh) * 32 + qw] = r;
    }
}

extern "C" void kernel_launch(void* const* d_in, const int* in_sizes, int n_in,
                              void* d_out, int out_size)
{
    const float* x    = (const float*)d_in[0];
    const float* wt   = (const float*)d_in[1];
    const float* bias = (const float*)d_in[2];
    float*       out  = (float*)d_out;

    svct_kernel<<<1024, 128>>>(x, wt, bias, out);
}